// round 9
// baseline (speedup 1.0000x reference)
#include <cuda_runtime.h>
#include <math.h>

// Problem constants
#define BTOT    262144
#define NBR     21
#define NDIM    16
#define FEATD   336      // 21*16
#define H1D     256
#define H2D     128
#define NATT    20
#define NAMT    30
#define NNODES  100000

// Tiling
#define MT       64      // samples per CTA
#define NTHREADS 512
#define HSTR     68      // padded stride for h1T/h2T

struct SM {
    float featT[FEATD][MT];   // K-major feature tile  (336*64)
    float h1T[H1D][HSTR];     // hidden1, K-major      (256*68)
    float h2T[H2D][HSTR];     // hidden2, K-major      (128*68)
    float wbuf[2][2048];      // double-buffered weight chunks / small-layer weights
    float logits[MT][33];     // padded (33) logits per sample
    float bbuf[512];          // [0..255] bias, [256..511] last w1-row for amt path
    float mv[MT];             // masked_value per sample
    int   cols[MT * NBR];     // gathered edge column ids
};

// ---------------------------------------------------------------------------
// packed fp32x2 helpers (sm_100a): bit-identical per-lane IEEE fp32 FMA
// ---------------------------------------------------------------------------
union F2 { unsigned long long u; float2 f; };

__device__ __forceinline__ void fma2(unsigned long long& c,
                                     unsigned long long a,
                                     unsigned long long b) {
    asm("fma.rn.f32x2 %0, %1, %2, %0;" : "+l"(c) : "l"(a), "l"(b));
}
__device__ __forceinline__ unsigned long long pack2(float lo, float hi) {
    unsigned long long r;
    asm("mov.b64 %0, {%1, %2};" : "=l"(r) : "f"(lo), "f"(hi));
    return r;
}

// ---------------------------------------------------------------------------
// JAX PARTITIONABLE threefry2x32 bits (default since jax 0.4.36):
// counter=(0, flat_idx), key=(0,1), output = lane0 ^ lane1. Then the jax
// uniform bit-trick and gumbel = -log(-log(u)).
// ---------------------------------------------------------------------------
__device__ __forceinline__ float gumbel_at(unsigned t) {
    const unsigned ks0 = 0u, ks1 = 1u, ks2 = 0x1BD11BDBu;
    unsigned ksv[3] = {ks0, ks1, ks2};
    unsigned x0 = 0u + ks0;
    unsigned x1 = t  + ks1;
    const int R0[4] = {13, 15, 26, 6};
    const int R1[4] = {17, 29, 16, 24};
#pragma unroll
    for (int i = 0; i < 5; i++) {
#pragma unroll
        for (int j = 0; j < 4; j++) {
            int r = (i & 1) ? R1[j] : R0[j];
            x0 += x1;
            x1 = (x1 << r) | (x1 >> (32 - r));
            x1 ^= x0;
        }
        x0 += ksv[(i + 1) % 3];
        x1 += ksv[(i + 2) % 3] + (unsigned)(i + 1);
    }
    unsigned bits = x0 ^ x1;
    float u = __uint_as_float((bits >> 9) | 0x3f800000u) - 1.0f;
    u = fmaxf(u, 1.17549435e-38f);
    return -logf(-logf(u));
}

// ---------------------------------------------------------------------------
// Fused tiled GEMM, f32x2, accumulators packed along M.
//   dstT[n][m] = relu( sum_k srcT[k][m]*Wg[k][n] + bias[n] (+ mv[m]*wlast[n]) )
// 512 threads / 16 warps. Warp tile: (4*MPT) rows x 32 cols; WMC warps in M.
// Lane: lm=lane>>3 (4 M-groups of MPT), ln=lane&7 (8 N-groups of 4).
// a-pairs load directly from m-contiguous smem (ulonglong2) -> no dup movs.
// Weights streamed from L2 in 8-row chunks, double buffered.
// Per-element accumulation order identical to prior rounds (bit-exact).
// ---------------------------------------------------------------------------
template<int K, int N, int SSTR, int WMC, int MPT>
__device__ __forceinline__ void gemm_block(
    const float* __restrict__ srcT, float* __restrict__ dstT, int dstr,
    const float* __restrict__ Wg, SM& s,
    const float* __restrict__ bias_sm,
    const float* __restrict__ mvp, const float* __restrict__ wlast_sm,
    int t)
{
    const int lane  = t & 31;
    const int warp  = t >> 5;
    const int wm    = warp % WMC;
    const int wn    = warp / WMC;
    const int mbase = wm * (4 * MPT) + (lane >> 3) * MPT;
    const int nbase = wn * 32 + (lane & 7) * 4;
    constexpr int MP  = MPT / 2;     // M-pairs per thread
    constexpr int NKB = K / 8;

    // preload chunk 0 (8*N floats, all 512 threads)
    {
        if constexpr (N == 256) {
            int idx = t * 4;
            *reinterpret_cast<float4*>(&s.wbuf[0][idx]) =
                *reinterpret_cast<const float4*>(&Wg[idx]);
        } else {
            int idx = t * 2;
            *reinterpret_cast<float2*>(&s.wbuf[0][idx]) =
                *reinterpret_cast<const float2*>(&Wg[idx]);
        }
    }
    __syncthreads();   // also orders caller's srcT / bias stores

    unsigned long long c2[MP][4];
#pragma unroll
    for (int n = 0; n < 4; n++) {
        float bv = bias_sm[nbase + n];
        unsigned long long bp = pack2(bv, bv);
#pragma unroll
        for (int p = 0; p < MP; p++) c2[p][n] = bp;
    }

    for (int kb = 0; kb < NKB; kb++) {
        const float* cur = s.wbuf[kb & 1];
        float* nxt = s.wbuf[(kb & 1) ^ 1];
        if (kb + 1 < NKB) {
            const float* src = Wg + (kb + 1) * 8 * N;
            if constexpr (N == 256) {
                int idx = t * 4;
                *reinterpret_cast<float4*>(&nxt[idx]) =
                    *reinterpret_cast<const float4*>(&src[idx]);
            } else {
                int idx = t * 2;
                *reinterpret_cast<float2*>(&nxt[idx]) =
                    *reinterpret_cast<const float2*>(&src[idx]);
            }
        }
#pragma unroll
        for (int kc = 0; kc < 8; kc++) {
            const float* arow = srcT + (kb * 8 + kc) * SSTR + mbase;
            unsigned long long a2[MP];
#pragma unroll
            for (int v = 0; v < MPT / 4; v++) {
                ulonglong2 av = reinterpret_cast<const ulonglong2*>(arow)[v];
                a2[v * 2 + 0] = av.x;
                a2[v * 2 + 1] = av.y;
            }
            float4 bf = *reinterpret_cast<const float4*>(&cur[kc * N + nbase]);
            unsigned long long b2[4] = {
                pack2(bf.x, bf.x), pack2(bf.y, bf.y),
                pack2(bf.z, bf.z), pack2(bf.w, bf.w)
            };
#pragma unroll
            for (int p = 0; p < MP; p++)
#pragma unroll
                for (int n = 0; n < 4; n++)
                    fma2(c2[p][n], a2[p], b2[n]);
        }
        __syncthreads();
    }

    if (mvp != nullptr) {   // extra K-term: concat(feature, masked_value)
        unsigned long long a2[MP];
#pragma unroll
        for (int v = 0; v < MPT / 4; v++) {
            ulonglong2 av = reinterpret_cast<const ulonglong2*>(mvp + mbase)[v];
            a2[v * 2 + 0] = av.x;
            a2[v * 2 + 1] = av.y;
        }
#pragma unroll
        for (int n = 0; n < 4; n++) {
            float wv = wlast_sm[nbase + n];
            unsigned long long wl = pack2(wv, wv);
#pragma unroll
            for (int p = 0; p < MP; p++)
                fma2(c2[p][n], a2[p], wl);
        }
    }

    // relu + store K-major (m-contiguous float4 stores)
#pragma unroll
    for (int n = 0; n < 4; n++) {
        float* drow = dstT + (nbase + n) * dstr + mbase;
#pragma unroll
        for (int v = 0; v < MPT / 4; v++) {
            F2 u0, u1;
            u0.u = c2[v * 2 + 0][n];
            u1.u = c2[v * 2 + 1][n];
            float4 o;
            o.x = fmaxf(u0.f.x, 0.0f);
            o.y = fmaxf(u0.f.y, 0.0f);
            o.z = fmaxf(u1.f.x, 0.0f);
            o.w = fmaxf(u1.f.y, 0.0f);
            reinterpret_cast<float4*>(drow)[v] = o;
        }
    }
}

__global__ __launch_bounds__(NTHREADS, 1)
void att_amt_policy_kernel(
    const float* __restrict__ x,
    const int* __restrict__ edge_col,            // edge_index row 1 (int32)
    const float* __restrict__ actual_amount,
    const int* __restrict__ real_act,            // int32
    const float* __restrict__ att_w1, const float* __restrict__ att_b1,
    const float* __restrict__ att_w2, const float* __restrict__ att_b2,
    const float* __restrict__ att_w3, const float* __restrict__ att_b3,
    const float* __restrict__ amt_w1, const float* __restrict__ amt_b1,
    const float* __restrict__ amt_w2, const float* __restrict__ amt_b2,
    const float* __restrict__ amt_w3, const float* __restrict__ amt_b3,
    float* __restrict__ out)
{
    extern __shared__ char smraw[];
    SM& s = *reinterpret_cast<SM*>(smraw);
    const int t    = threadIdx.x;
    const int base = blockIdx.x * MT;
    float* wflat = &s.wbuf[0][0];

    // ---------------- phase 0: cols (coalesced), masked_value ----------------
    for (int p = t; p < MT * NBR; p += NTHREADS) {
        int c = edge_col[(long long)base * NBR + p];
        c = min(max(c, 0), NNODES - 1);          // defensive clamp
        s.cols[p] = c;
    }
    if (t < MT) {
        int i = base + t;
        int r = real_act[i];
        r = min(max(r, 0), NBR - 1);             // defensive clamp
        const float* aarow = actual_amount + (long long)i * NBR * 2;
        float p0  = aarow[r * 2 + 0];
        float p1  = aarow[r * 2 + 1];
        float a00 = aarow[0];
        s.mv[t] = (a00 > 0.0f) ? p0 : -p1;
    }
    __syncthreads();

    // ---------------- phase 1: gather features ------------------------------
    for (int q = t; q < MT * NBR; q += NTHREADS) {
        int ss = q & (MT - 1);
        int j  = q >> 6;                       // MT == 64
        int node = s.cols[ss * NBR + j];
        const float4* xr = reinterpret_cast<const float4*>(x + (long long)node * NDIM);
#pragma unroll
        for (int v = 0; v < 4; v++) {
            float4 w = xr[v];
            s.featT[j * NDIM + v * 4 + 0][ss] = w.x;
            s.featT[j * NDIM + v * 4 + 1][ss] = w.y;
            s.featT[j * NDIM + v * 4 + 2][ss] = w.z;
            s.featT[j * NDIM + v * 4 + 3][ss] = w.w;
        }
    }
    // (gemm_block's first __syncthreads orders these stores)

    // ============================ ATT branch ================================
    for (int p = t; p < H1D; p += NTHREADS) s.bbuf[p] = att_b1[p];
    gemm_block<FEATD, H1D, MT, 2, 8>(&s.featT[0][0], &s.h1T[0][0], HSTR,
                                     att_w1, s, s.bbuf, nullptr, nullptr, t);

    for (int p = t; p < H2D; p += NTHREADS) s.bbuf[p] = att_b2[p];
    gemm_block<H1D, H2D, HSTR, 4, 4>(&s.h1T[0][0], &s.h2T[0][0], HSTR,
                                     att_w2, s, s.bbuf, nullptr, nullptr, t);

    // GEMM3 att: 64x20, K=128 (threads t<256)
    for (int p = t; p < H2D * NATT; p += NTHREADS) wflat[p] = att_w3[p];
    __syncthreads();
    if (t < 256) {
        int ssp = t & 63;
        int g   = t >> 6;                      // 4 groups x 5 outputs
        float acc[5];
#pragma unroll
        for (int j = 0; j < 5; j++) acc[j] = att_b3[g * 5 + j];
        for (int k = 0; k < H2D; k++) {
            float a = s.h2T[k][ssp];
#pragma unroll
            for (int j = 0; j < 5; j++)
                acc[j] = fmaf(a, wflat[k * NATT + g * 5 + j], acc[j]);
        }
#pragma unroll
        for (int j = 0; j < 5; j++) s.logits[ssp][g * 5 + j] = acc[j];
    }
    __syncthreads();

    // att softmax + store : 4 threads per sample (same warp nibble)
    if (t < 256) {
        int ss = t >> 2, q = t & 3;
        int i = base + ss;
        float l[5];
        float mx = -1e30f;
#pragma unroll
        for (int j = 0; j < 5; j++) {
            l[j] = s.logits[ss][q * 5 + j];
            mx = fmaxf(mx, l[j]);
        }
        mx = fmaxf(mx, __shfl_xor_sync(0xffffffffu, mx, 1));
        mx = fmaxf(mx, __shfl_xor_sync(0xffffffffu, mx, 2));
        float sum = 0.f;
#pragma unroll
        for (int j = 0; j < 5; j++) { l[j] = expf(l[j] - mx); sum += l[j]; }
        sum += __shfl_xor_sync(0xffffffffu, sum, 1);
        sum += __shfl_xor_sync(0xffffffffu, sum, 2);
        float inv = 1.0f / sum;
        float* od = out + (size_t)BTOT + (size_t)i * NATT;
#pragma unroll
        for (int j = 0; j < 5; j++) od[q * 5 + j] = l[j] * inv;
    }
    __syncthreads();

    // ============================ AMT branch ================================
    for (int p = t; p < H1D; p += NTHREADS) {
        s.bbuf[p]       = amt_b1[p];
        s.bbuf[256 + p] = amt_w1[(size_t)FEATD * H1D + p];  // row 336 (masked_value)
    }
    gemm_block<FEATD, H1D, MT, 2, 8>(&s.featT[0][0], &s.h1T[0][0], HSTR,
                                     amt_w1, s, s.bbuf, s.mv, s.bbuf + 256, t);

    for (int p = t; p < H2D; p += NTHREADS) s.bbuf[p] = amt_b2[p];
    gemm_block<H1D, H2D, HSTR, 4, 4>(&s.h1T[0][0], &s.h2T[0][0], HSTR,
                                     amt_w2, s, s.bbuf, nullptr, nullptr, t);

    // GEMM3 amt: 64x30, K=128 (threads t<256)
    for (int p = t; p < H2D * NAMT; p += NTHREADS) wflat[p] = amt_w3[p];
    __syncthreads();
    if (t < 256) {
        int ssp = t & 63;
        int g   = t >> 6;                      // groups of 8 (last has 6)
        int n0  = g * 8;
        float acc[8];
#pragma unroll
        for (int j = 0; j < 8; j++)
            acc[j] = (n0 + j < NAMT) ? amt_b3[n0 + j] : 0.f;
        for (int k = 0; k < H2D; k++) {
            float a = s.h2T[k][ssp];
#pragma unroll
            for (int j = 0; j < 8; j++)
                if (n0 + j < NAMT)
                    acc[j] = fmaf(a, wflat[k * NAMT + n0 + j], acc[j]);
        }
#pragma unroll
        for (int j = 0; j < 8; j++)
            if (n0 + j < NAMT) s.logits[ssp][n0 + j] = acc[j];
    }
    __syncthreads();

    // --- amt softmax -> mask -> softmax -> gumbel argmax : 4 thr/sample -----
    if (t < 256) {
        int ss = t >> 2, q = t & 3;
        int i = base + ss;
        int nbase = q * 8;                     // q=3 covers 24..29 (6 valid)
        float l[8];
        float mx = -1e30f;
#pragma unroll
        for (int j = 0; j < 8; j++) {
            int n = nbase + j;
            l[j] = (n < NAMT) ? s.logits[ss][n] : -1e30f;
            mx = fmaxf(mx, l[j]);
        }
        mx = fmaxf(mx, __shfl_xor_sync(0xffffffffu, mx, 1));
        mx = fmaxf(mx, __shfl_xor_sync(0xffffffffu, mx, 2));
        float sum = 0.f;
#pragma unroll
        for (int j = 0; j < 8; j++) {
            int n = nbase + j;
            float e = (n < NAMT) ? expf(l[j] - mx) : 0.f;
            l[j] = e;
            sum += e;
        }
        sum += __shfl_xor_sync(0xffffffffu, sum, 1);
        sum += __shfl_xor_sync(0xffffffffu, sum, 2);
        float inv = 1.0f / sum;
#pragma unroll
        for (int j = 0; j < 8; j++) l[j] *= inv;     // amt_probs

        // bucket threshold: clamp(ceil((mv/0.1)/2), 1, 30)
        float mvv = s.mv[ss];
        float a1 = mvv / 0.1f;
        a1 = a1 / 2.0f;
        float cf = ceilf(a1);
        cf = fminf(fmaxf(cf, 1.0f), 30.0f);
        int temp = (int)cf;

        // second (masked) softmax over first `temp` buckets
        float mx2 = -1e30f;
#pragma unroll
        for (int j = 0; j < 8; j++)
            if (nbase + j < temp) mx2 = fmaxf(mx2, l[j]);
        mx2 = fmaxf(mx2, __shfl_xor_sync(0xffffffffu, mx2, 1));
        mx2 = fmaxf(mx2, __shfl_xor_sync(0xffffffffu, mx2, 2));
        float sum2 = 0.f;
#pragma unroll
        for (int j = 0; j < 8; j++) {
            float e = (nbase + j < temp) ? expf(l[j] - mx2) : 0.f;
            l[j] = e;
            sum2 += e;
        }
        sum2 += __shfl_xor_sync(0xffffffffu, sum2, 1);
        sum2 += __shfl_xor_sync(0xffffffffu, sum2, 2);
        float inv2 = 1.0f / sum2;

        float* od = out + (size_t)BTOT * (1 + NATT) + (size_t)i * NAMT;
        int best = NAMT;                       // sentinel > any valid idx
        float bestsc = -1e30f;
        unsigned gbase = (unsigned)i * (unsigned)NAMT;
#pragma unroll
        for (int j = 0; j < 8; j++) {
            int n = nbase + j;
            if (n < NAMT) {
                float a = l[j] * inv2;         // exact 0 for masked buckets
                od[n] = a;
                float sc = logf(a + 1e-20f) + gumbel_at(gbase + n);
                if (sc > bestsc) { bestsc = sc; best = n; }
            }
        }
        // nibble argmax reduce; first-index wins on exact ties
#pragma unroll
        for (int off = 1; off < 4; off <<= 1) {
            float osc = __shfl_xor_sync(0xffffffffu, bestsc, off);
            int   obn = __shfl_xor_sync(0xffffffffu, best, off);
            if (osc > bestsc || (osc == bestsc && obn < best)) {
                bestsc = osc; best = obn;
            }
        }
        if (q == 0) out[i] = (float)best;      // cnt
    }
}

extern "C" void kernel_launch(void* const* d_in, const int* in_sizes, int n_in,
                              void* d_out, int out_size) {
    const float* x  = (const float*)d_in[0];
    const int*   ei = (const int*)d_in[1];      // int32 (jax x64 disabled)
    const float* aa = (const float*)d_in[2];
    const int*   ra = (const int*)d_in[3];      // int32
    const float *aw1 = (const float*)d_in[4],  *ab1 = (const float*)d_in[5];
    const float *aw2 = (const float*)d_in[6],  *ab2 = (const float*)d_in[7];
    const float *aw3 = (const float*)d_in[8],  *ab3 = (const float*)d_in[9];
    const float *mw1 = (const float*)d_in[10], *mb1 = (const float*)d_in[11];
    const float *mw2 = (const float*)d_in[12], *mb2 = (const float*)d_in[13];
    const float *mw3 = (const float*)d_in[14], *mb3 = (const float*)d_in[15];
    float* out = (float*)d_out;

    cudaFuncSetAttribute(att_amt_policy_kernel,
                         cudaFuncAttributeMaxDynamicSharedMemorySize,
                         (int)sizeof(SM));
    const int* edge_col = ei + (long long)BTOT * NBR;  // edge_index[1]
    att_amt_policy_kernel<<<BTOT / MT, NTHREADS, sizeof(SM)>>>(
        x, edge_col, aa, ra,
        aw1, ab1, aw2, ab2, aw3, ab3,
        mw1, mb1, mw2, mb2, mw3, mb3,
        out);
}

// round 11
// speedup vs baseline: 1.2461x; 1.2461x over previous
#include <cuda_runtime.h>
#include <math.h>
#include <stdint.h>

// Problem constants
#define BTOT    262144
#define NBR     21
#define NDIM    16
#define FEATD   336      // 21*16
#define H1D     256
#define H2D     128
#define NATT    20
#define NAMT    30
#define NNODES  100000

// Tiling
#define MT       64      // samples per CTA
#define NTHREADS 512
#define HSTR     68      // padded stride for h1T/h2T

typedef unsigned long long ull;

struct SM {
    float featT[FEATD][MT];       // 86016 B : K-major feature tile
    float h1T[H1D][HSTR];         // 69632 B : hidden1, K-major
    union {
        float h2T[H2D][HSTR];     // 34816 B : hidden2, K-major
        struct {
            float wpipe[16][4][128]; // 32768 B : per-warp 4-stage weight pipeline
            float extra[512];        //  2048 B : amt wlast row
        } p;
    } u;
    float wflat[4096];            // 16384 B : GEMM3 weights
    float logits[MT][33];         //  8448 B
    float bbuf[512];              //  2048 B : [0:256]=b1, [256:384]=b2
    float mv[MT];                 //   256 B
    int   cols[MT * NBR];         //  5376 B
};                                // total 222976 B

// ---------------------------------------------------------------------------
// packed fp32x2 helpers (bit-identical per-lane IEEE fp32 FMA)
// ---------------------------------------------------------------------------
union F2 { ull u; float2 f; };

__device__ __forceinline__ void fma2(ull& c, ull a, ull b) {
    asm("fma.rn.f32x2 %0, %1, %2, %0;" : "+l"(c) : "l"(a), "l"(b));
}
__device__ __forceinline__ ull pack2(float lo, float hi) {
    ull r;
    asm("mov.b64 %0, {%1, %2};" : "=l"(r) : "f"(lo), "f"(hi));
    return r;
}

// ---------------------------------------------------------------------------
// cp.async helpers (per-warp weight streaming)
// ---------------------------------------------------------------------------
__device__ __forceinline__ void cpa16(uint32_t s, const float* g) {
    asm volatile("cp.async.ca.shared.global [%0], [%1], 16;" :: "r"(s), "l"(g));
}
__device__ __forceinline__ void cp_commit() { asm volatile("cp.async.commit_group;"); }
__device__ __forceinline__ void cp_wait0() { asm volatile("cp.async.wait_group 0;"); }
__device__ __forceinline__ void cp_wait1() { asm volatile("cp.async.wait_group 1;"); }
__device__ __forceinline__ void cp_wait2() { asm volatile("cp.async.wait_group 2;"); }
__device__ __forceinline__ void cp_wait3() { asm volatile("cp.async.wait_group 3;"); }

// Issue one 8-row x 16-col weight chunk into a pipeline stage (one warp).
// Thread: row = lane>>2, 16B block = lane&3. 512 B total, one commit group.
template<int N>
__device__ __forceinline__ void issue_chunk(const float* __restrict__ Wg, int k0,
                                            int ncol0, uint32_t stage_b, int lane) {
    int row = lane >> 2;
    int c16 = lane & 3;
    cpa16(stage_b + row * 64 + c16 * 16,
          Wg + (size_t)(k0 + row) * N + ncol0 + c16 * 4);
    cp_commit();
}

// ---------------------------------------------------------------------------
// JAX PARTITIONABLE threefry2x32 bits: counter=(0,idx), key=(0,1),
// bits = lane0 ^ lane1; jax uniform bit-trick; gumbel = -log(-log(u)).
// ---------------------------------------------------------------------------
__device__ __forceinline__ float gumbel_at(unsigned t) {
    const unsigned ks0 = 0u, ks1 = 1u, ks2 = 0x1BD11BDBu;
    unsigned ksv[3] = {ks0, ks1, ks2};
    unsigned x0 = 0u + ks0;
    unsigned x1 = t  + ks1;
    const int R0[4] = {13, 15, 26, 6};
    const int R1[4] = {17, 29, 16, 24};
#pragma unroll
    for (int i = 0; i < 5; i++) {
#pragma unroll
        for (int j = 0; j < 4; j++) {
            int r = (i & 1) ? R1[j] : R0[j];
            x0 += x1;
            x1 = (x1 << r) | (x1 >> (32 - r));
            x1 ^= x0;
        }
        x0 += ksv[(i + 1) % 3];
        x1 += ksv[(i + 2) % 3] + (unsigned)(i + 1);
    }
    unsigned bits = x0 ^ x1;
    float u = __uint_as_float((bits >> 9) | 0x3f800000u) - 1.0f;
    u = fmaxf(u, 1.17549435e-38f);
    return -logf(-logf(u));
}

// ---------------------------------------------------------------------------
// Barrier-free pipelined GEMM. Each warp owns 16 output cols and streams its
// weight slice via cp.async (4 stages, 3-deep prefetch, private buffer).
// Caller must have issued chunks 0..2 already (issue_chunk x3 + commits).
//   dstT[n][m] = relu( sum_k srcT[k][m]*W[k][n] + bias[n] (+ mv[m]*wlast[n]) )
// WMC=1: warp covers all 64 rows (MP=8). WMC=2: wm=warp&1 covers 32 rows.
// Lane map: lm=lane>>3 owns rows {blk*32 + lm*8 + 0..7}; ln=lane&7 owns 2 cols.
// Per-element k-order identical to prior rounds (bit-exact logits).
// ---------------------------------------------------------------------------
template<int K, int N, int WMC, bool HASMV, bool BAR_BEFORE_STORE>
__device__ __forceinline__ void gemm_pipe(
    SM& s, const float* __restrict__ srcT, int sstr,
    float* __restrict__ dstT, int dstr,
    const float* __restrict__ Wg,
    const float* __restrict__ bias_sm,
    const float* __restrict__ mvp, const float* __restrict__ wlast_sm,
    int t)
{
    const int lane   = t & 31;
    const int warp   = t >> 5;
    const int wn     = warp / WMC;
    const int wmbase = (warp % WMC) * 32;   // 0 when WMC==1
    const int lm     = lane >> 3;
    const int ln     = lane & 7;
    const int nc0    = wn * 16 + ln * 2;
    constexpr int MP  = 8 / WMC;            // accumulator pairs (M per thread / 2)
    constexpr int NV  = MP / 2;             // 16B a-loads per kc
    constexpr int NKB = K / 8;

    float* wsl = &s.u.p.wpipe[warp][0][0];
    uint32_t wslb = (uint32_t)__cvta_generic_to_shared(wsl);

    ull c2[MP][2];
#pragma unroll
    for (int c = 0; c < 2; c++) {
        float bv = bias_sm[nc0 + c];
        ull bp = pack2(bv, bv);
#pragma unroll
        for (int p = 0; p < MP; p++) c2[p][c] = bp;
    }

#pragma unroll 1
    for (int kb = 0; kb < NKB; kb++) {
        if (kb + 3 < NKB) {
            issue_chunk<N>(Wg, (kb + 3) * 8, wn * 16, wslb + ((kb + 3) & 3) * 512, lane);
            cp_wait3();
        } else if (kb + 2 < NKB) cp_wait2();
        else if (kb + 1 < NKB)   cp_wait1();
        else                     cp_wait0();
        __syncwarp();

        const float* cw = wsl + (kb & 3) * 128;
#pragma unroll
        for (int kc = 0; kc < 8; kc++) {
            const float* ar = srcT + (kb * 8 + kc) * sstr + wmbase;
            ull a2[MP];
#pragma unroll
            for (int v = 0; v < NV; v++) {
                ulonglong2 av = *reinterpret_cast<const ulonglong2*>(
                    ar + (v >> 1) * 32 + lm * 8 + (v & 1) * 4);
                a2[2 * v + 0] = av.x;
                a2[2 * v + 1] = av.y;
            }
            float2 bf = *reinterpret_cast<const float2*>(cw + kc * 16 + ln * 2);
            ull b2[2] = { pack2(bf.x, bf.x), pack2(bf.y, bf.y) };
#pragma unroll
            for (int p = 0; p < MP; p++)
#pragma unroll
                for (int c = 0; c < 2; c++)
                    fma2(c2[p][c], a2[p], b2[c]);
        }
    }

    if (HASMV) {   // extra K-term: concat(feature, masked_value)
        ull a2[MP];
#pragma unroll
        for (int v = 0; v < NV; v++) {
            ulonglong2 av = *reinterpret_cast<const ulonglong2*>(
                mvp + wmbase + (v >> 1) * 32 + lm * 8 + (v & 1) * 4);
            a2[2 * v + 0] = av.x;
            a2[2 * v + 1] = av.y;
        }
#pragma unroll
        for (int c = 0; c < 2; c++) {
            float wv = wlast_sm[nc0 + c];
            ull wl = pack2(wv, wv);
#pragma unroll
            for (int p = 0; p < MP; p++)
                fma2(c2[p][c], a2[p], wl);
        }
    }

    if (BAR_BEFORE_STORE) __syncthreads();  // dst aliases other warps' wpipe

    // relu + store K-major
#pragma unroll
    for (int c = 0; c < 2; c++) {
        float* dr = dstT + (nc0 + c) * dstr + wmbase;
#pragma unroll
        for (int v = 0; v < NV; v++) {
            F2 u0, u1;
            u0.u = c2[2 * v + 0][c];
            u1.u = c2[2 * v + 1][c];
            float4 o;
            o.x = fmaxf(u0.f.x, 0.0f);
            o.y = fmaxf(u0.f.y, 0.0f);
            o.z = fmaxf(u1.f.x, 0.0f);
            o.w = fmaxf(u1.f.y, 0.0f);
            *reinterpret_cast<float4*>(dr + (v >> 1) * 32 + lm * 8 + (v & 1) * 4) = o;
        }
    }
}

__global__ __launch_bounds__(NTHREADS, 1)
void att_amt_policy_kernel(
    const float* __restrict__ x,
    const int* __restrict__ edge_col,            // edge_index row 1 (int32)
    const float* __restrict__ actual_amount,
    const int* __restrict__ real_act,            // int32
    const float* __restrict__ att_w1, const float* __restrict__ att_b1,
    const float* __restrict__ att_w2, const float* __restrict__ att_b2,
    const float* __restrict__ att_w3, const float* __restrict__ att_b3,
    const float* __restrict__ amt_w1, const float* __restrict__ amt_b1,
    const float* __restrict__ amt_w2, const float* __restrict__ amt_b2,
    const float* __restrict__ amt_w3, const float* __restrict__ amt_b3,
    float* __restrict__ out)
{
    extern __shared__ char smraw[];
    SM& s = *reinterpret_cast<SM*>(smraw);
    const int t    = threadIdx.x;
    const int lane = t & 31;
    const int warp = t >> 5;
    const int base = blockIdx.x * MT;
    uint32_t wslb = (uint32_t)__cvta_generic_to_shared(&s.u.p.wpipe[warp][0][0]);

    // ---- ATT GEMM1 weight preload (overlaps gather; own-region, no hazard) --
#pragma unroll
    for (int c = 0; c < 3; c++)
        issue_chunk<H1D>(att_w1, c * 8, warp * 16, wslb + c * 512, lane);

    // ---------------- phase 0: cols (coalesced), masked_value ----------------
    for (int p = t; p < MT * NBR; p += NTHREADS) {
        int c = edge_col[(long long)base * NBR + p];
        c = min(max(c, 0), NNODES - 1);          // defensive clamp
        s.cols[p] = c;
    }
    if (t < MT) {
        int i = base + t;
        int r = real_act[i];
        r = min(max(r, 0), NBR - 1);             // defensive clamp
        const float* aarow = actual_amount + (long long)i * NBR * 2;
        float p0  = aarow[r * 2 + 0];
        float p1  = aarow[r * 2 + 1];
        float a00 = aarow[0];
        s.mv[t] = (a00 > 0.0f) ? p0 : -p1;
    }
    // att biases
    for (int p = t; p < H1D; p += NTHREADS) s.bbuf[p] = att_b1[p];
    for (int p = t; p < H2D; p += NTHREADS) s.bbuf[256 + p] = att_b2[p];
    __syncthreads();

    // ---------------- phase 1: gather features ------------------------------
    for (int q = t; q < MT * NBR; q += NTHREADS) {
        int ss = q & (MT - 1);
        int j  = q >> 6;                       // MT == 64
        int node = s.cols[ss * NBR + j];
        const float4* xr = reinterpret_cast<const float4*>(x + (long long)node * NDIM);
#pragma unroll
        for (int v = 0; v < 4; v++) {
            float4 w = xr[v];
            s.featT[j * NDIM + v * 4 + 0][ss] = w.x;
            s.featT[j * NDIM + v * 4 + 1][ss] = w.y;
            s.featT[j * NDIM + v * 4 + 2][ss] = w.z;
            s.featT[j * NDIM + v * 4 + 3][ss] = w.w;
        }
    }
    __syncthreads();   // featT ready (B1)

    // ============================ ATT branch ================================
    gemm_pipe<FEATD, H1D, 1, false, false>(s, &s.featT[0][0], MT,
                                           &s.h1T[0][0], HSTR,
                                           att_w1, s.bbuf, nullptr, nullptr, t);
    // preload ATT GEMM2 weights (own region; all GEMM1 groups drained)
#pragma unroll
    for (int c = 0; c < 3; c++)
        issue_chunk<H2D>(att_w2, c * 8, (warp >> 1) * 16, wslb + c * 512, lane);
    __syncthreads();   // h1T ready (B2)

    gemm_pipe<H1D, H2D, 2, false, true>(s, &s.h1T[0][0], HSTR,
                                        &s.u.h2T[0][0], HSTR,
                                        att_w2, s.bbuf + 256, nullptr, nullptr, t);
    // load att_w3
    for (int p = t; p < H2D * NATT; p += NTHREADS) s.wflat[p] = att_w3[p];
    __syncthreads();   // h2T + wflat ready (B4)

    // GEMM3 att: 64x20, K=128 (threads t<256)
    if (t < 256) {
        int ssp = t & 63;
        int g   = t >> 6;                      // 4 groups x 5 outputs
        float acc[5];
#pragma unroll
        for (int j = 0; j < 5; j++) acc[j] = att_b3[g * 5 + j];
        for (int k = 0; k < H2D; k++) {
            float a = s.u.h2T[k][ssp];
#pragma unroll
            for (int j = 0; j < 5; j++)
                acc[j] = fmaf(a, s.wflat[k * NATT + g * 5 + j], acc[j]);
        }
#pragma unroll
        for (int j = 0; j < 5; j++) s.logits[ssp][g * 5 + j] = acc[j];
    }
    __syncthreads();   // logits ready; h2T dead (B5)

    // preload AMT GEMM1 weights (h2T region now dead)
#pragma unroll
    for (int c = 0; c < 3; c++)
        issue_chunk<H1D>(amt_w1, c * 8, warp * 16, wslb + c * 512, lane);

    // att softmax + store : 4 threads per sample
    if (t < 256) {
        int ss = t >> 2, q = t & 3;
        int i = base + ss;
        float l[5];
        float mx = -1e30f;
#pragma unroll
        for (int j = 0; j < 5; j++) {
            l[j] = s.logits[ss][q * 5 + j];
            mx = fmaxf(mx, l[j]);
        }
        mx = fmaxf(mx, __shfl_xor_sync(0xffffffffu, mx, 1));
        mx = fmaxf(mx, __shfl_xor_sync(0xffffffffu, mx, 2));
        float sum = 0.f;
#pragma unroll
        for (int j = 0; j < 5; j++) { l[j] = expf(l[j] - mx); sum += l[j]; }
        sum += __shfl_xor_sync(0xffffffffu, sum, 1);
        sum += __shfl_xor_sync(0xffffffffu, sum, 2);
        float inv = 1.0f / sum;
        float* od = out + (size_t)BTOT + (size_t)i * NATT;
#pragma unroll
        for (int j = 0; j < 5; j++) od[q * 5 + j] = l[j] * inv;
    }
    // amt biases + wlast (att copies dead)
    for (int p = t; p < H1D; p += NTHREADS) {
        s.bbuf[p] = amt_b1[p];
        s.u.p.extra[p & 255] = amt_w1[(size_t)FEATD * H1D + p];  // p<256 path only
    }
    for (int p = t; p < H2D; p += NTHREADS) s.bbuf[256 + p] = amt_b2[p];
    __syncthreads();   // (B6)

    // ============================ AMT branch ================================
    gemm_pipe<FEATD, H1D, 1, true, false>(s, &s.featT[0][0], MT,
                                          &s.h1T[0][0], HSTR,
                                          amt_w1, s.bbuf, s.mv, s.u.p.extra, t);
#pragma unroll
    for (int c = 0; c < 3; c++)
        issue_chunk<H2D>(amt_w2, c * 8, (warp >> 1) * 16, wslb + c * 512, lane);
    __syncthreads();   // h1T ready (B7)

    gemm_pipe<H1D, H2D, 2, false, true>(s, &s.h1T[0][0], HSTR,
                                        &s.u.h2T[0][0], HSTR,
                                        amt_w2, s.bbuf + 256, nullptr, nullptr, t);
    for (int p = t; p < H2D * NAMT; p += NTHREADS) s.wflat[p] = amt_w3[p];
    __syncthreads();   // h2T + wflat ready (B8)

    // GEMM3 amt: 64x30, K=128 (threads t<256)
    if (t < 256) {
        int ssp = t & 63;
        int g   = t >> 6;                      // groups of 8 (last has 6)
        int n0  = g * 8;
        float acc[8];
#pragma unroll
        for (int j = 0; j < 8; j++)
            acc[j] = (n0 + j < NAMT) ? amt_b3[n0 + j] : 0.f;
        for (int k = 0; k < H2D; k++) {
            float a = s.u.h2T[k][ssp];
#pragma unroll
            for (int j = 0; j < 8; j++)
                if (n0 + j < NAMT)
                    acc[j] = fmaf(a, s.wflat[k * NAMT + n0 + j], acc[j]);
        }
#pragma unroll
        for (int j = 0; j < 8; j++)
            if (n0 + j < NAMT) s.logits[ssp][n0 + j] = acc[j];
    }
    __syncthreads();   // (B9)

    // --- amt softmax -> mask -> softmax -> gumbel argmax : 4 thr/sample -----
    if (t < 256) {
        int ss = t >> 2, q = t & 3;
        int i = base + ss;
        int nbase = q * 8;                     // q=3 covers 24..29 (6 valid)
        float l[8];
        float mx = -1e30f;
#pragma unroll
        for (int j = 0; j < 8; j++) {
            int n = nbase + j;
            l[j] = (n < NAMT) ? s.logits[ss][n] : -1e30f;
            mx = fmaxf(mx, l[j]);
        }
        mx = fmaxf(mx, __shfl_xor_sync(0xffffffffu, mx, 1));
        mx = fmaxf(mx, __shfl_xor_sync(0xffffffffu, mx, 2));
        float sum = 0.f;
#pragma unroll
        for (int j = 0; j < 8; j++) {
            int n = nbase + j;
            float e = (n < NAMT) ? expf(l[j] - mx) : 0.f;
            l[j] = e;
            sum += e;
        }
        sum += __shfl_xor_sync(0xffffffffu, sum, 1);
        sum += __shfl_xor_sync(0xffffffffu, sum, 2);
        float inv = 1.0f / sum;
#pragma unroll
        for (int j = 0; j < 8; j++) l[j] *= inv;     // amt_probs

        // bucket threshold: clamp(ceil((mv/0.1)/2), 1, 30)
        float mvv = s.mv[ss];
        float a1 = mvv / 0.1f;
        a1 = a1 / 2.0f;
        float cf = ceilf(a1);
        cf = fminf(fmaxf(cf, 1.0f), 30.0f);
        int temp = (int)cf;

        // second (masked) softmax over first `temp` buckets
        float mx2 = -1e30f;
#pragma unroll
        for (int j = 0; j < 8; j++)
            if (nbase + j < temp) mx2 = fmaxf(mx2, l[j]);
        mx2 = fmaxf(mx2, __shfl_xor_sync(0xffffffffu, mx2, 1));
        mx2 = fmaxf(mx2, __shfl_xor_sync(0xffffffffu, mx2, 2));
        float sum2 = 0.f;
#pragma unroll
        for (int j = 0; j < 8; j++) {
            float e = (nbase + j < temp) ? expf(l[j] - mx2) : 0.f;
            l[j] = e;
            sum2 += e;
        }
        sum2 += __shfl_xor_sync(0xffffffffu, sum2, 1);
        sum2 += __shfl_xor_sync(0xffffffffu, sum2, 2);
        float inv2 = 1.0f / sum2;

        float* od = out + (size_t)BTOT * (1 + NATT) + (size_t)i * NAMT;
        int best = NAMT;
        float bestsc = -1e30f;
        unsigned gbase = (unsigned)i * (unsigned)NAMT;
#pragma unroll
        for (int j = 0; j < 8; j++) {
            int n = nbase + j;
            if (n < NAMT) {
                float a = l[j] * inv2;         // exact 0 for masked buckets
                od[n] = a;
                float sc = logf(a + 1e-20f) + gumbel_at(gbase + n);
                if (sc > bestsc) { bestsc = sc; best = n; }
            }
        }
#pragma unroll
        for (int off = 1; off < 4; off <<= 1) {
            float osc = __shfl_xor_sync(0xffffffffu, bestsc, off);
            int   obn = __shfl_xor_sync(0xffffffffu, best, off);
            if (osc > bestsc || (osc == bestsc && obn < best)) {
                bestsc = osc; best = obn;
            }
        }
        if (q == 0) out[i] = (float)best;      // cnt
    }
}

extern "C" void kernel_launch(void* const* d_in, const int* in_sizes, int n_in,
                              void* d_out, int out_size) {
    const float* x  = (const float*)d_in[0];
    const int*   ei = (const int*)d_in[1];      // int32 (jax x64 disabled)
    const float* aa = (const float*)d_in[2];
    const int*   ra = (const int*)d_in[3];      // int32
    const float *aw1 = (const float*)d_in[4],  *ab1 = (const float*)d_in[5];
    const float *aw2 = (const float*)d_in[6],  *ab2 = (const float*)d_in[7];
    const float *aw3 = (const float*)d_in[8],  *ab3 = (const float*)d_in[9];
    const float *mw1 = (const float*)d_in[10], *mb1 = (const float*)d_in[11];
    const float *mw2 = (const float*)d_in[12], *mb2 = (const float*)d_in[13];
    const float *mw3 = (const float*)d_in[14], *mb3 = (const float*)d_in[15];
    float* out = (float*)d_out;

    cudaFuncSetAttribute(att_amt_policy_kernel,
                         cudaFuncAttributeMaxDynamicSharedMemorySize,
                         (int)sizeof(SM));
    const int* edge_col = ei + (long long)BTOT * NBR;  // edge_index[1]
    att_amt_policy_kernel<<<BTOT / MT, NTHREADS, sizeof(SM)>>>(
        x, edge_col, aa, ra,
        aw1, ab1, aw2, ab2, aw3, ab3,
        mw1, mb1, mw2, mb2, mw3, mb3,
        out);
}